// round 1
// baseline (speedup 1.0000x reference)
#include <cuda_runtime.h>
#include <math_constants.h>

// PQHead: out[b, m*6+d] = codebooks[m, argmax_k <x[b,m*6:..], cb[m,k,:]>, d]
// (softmax path is identity in the forward value: quant == discrete)

#define B_ROWS   32768
#define M_SUB    128
#define K_CODES  32
#define D_SUB    6
#define DIM      768
#define RPT      8                       // rows per thread
#define TPB      256                     // threads per block (2 row-groups x 128 m)
#define ROWGRP   (TPB / M_SUB)           // 2
#define TILE_ROWS (RPT * ROWGRP)         // 16
#define NTILES   (B_ROWS / TILE_ROWS)    // 2048
#define NBLOCKS  296                     // 2 per SM, persistent
#define CB_ELEMS (M_SUB * K_CODES * D_SUB)   // 24576 floats = 96KB

__global__ void __launch_bounds__(TPB, 2)
pq_head_kernel(const float* __restrict__ x,
               const float* __restrict__ cb,
               float* __restrict__ out)
{
    // smem codebook, transposed: cbs[(k*6+d)*128 + m]
    // lane index == m  -> bank = m % 32 -> conflict-free, no padding needed.
    extern __shared__ float cbs[];

    const int t = threadIdx.x;

    // One-time codebook load (coalesced global read, scattered smem write).
    for (int i = t; i < CB_ELEMS; i += TPB) {
        int m  = i / (K_CODES * D_SUB);
        int kd = i - m * (K_CODES * D_SUB);
        cbs[kd * M_SUB + m] = cb[i];
    }
    __syncthreads();

    const int m = t & (M_SUB - 1);
    const int g = t >> 7;            // row-group within block: 0 or 1

    for (int tile = blockIdx.x; tile < NTILES; tile += gridDim.x) {
        const int b0 = tile * TILE_ROWS + g * RPT;

        // Load RPT rows' subvectors (24B each, 8B-aligned -> 3x float2).
        float xv[RPT][D_SUB];
        #pragma unroll
        for (int r = 0; r < RPT; r++) {
            const float2* p = reinterpret_cast<const float2*>(
                x + (size_t)(b0 + r) * DIM + m * D_SUB);
            float2 a = p[0], bq = p[1], c = p[2];
            xv[r][0] = a.x;  xv[r][1] = a.y;
            xv[r][2] = bq.x; xv[r][3] = bq.y;
            xv[r][4] = c.x;  xv[r][5] = c.y;
        }

        float best[RPT];
        int   idx[RPT];
        #pragma unroll
        for (int r = 0; r < RPT; r++) { best[r] = -CUDART_INF_F; idx[r] = 0; }

        #pragma unroll 4
        for (int k = 0; k < K_CODES; k++) {
            const int kb = k * D_SUB;
            const float c0 = cbs[(kb + 0) * M_SUB + m];
            const float c1 = cbs[(kb + 1) * M_SUB + m];
            const float c2 = cbs[(kb + 2) * M_SUB + m];
            const float c3 = cbs[(kb + 3) * M_SUB + m];
            const float c4 = cbs[(kb + 4) * M_SUB + m];
            const float c5 = cbs[(kb + 5) * M_SUB + m];
            #pragma unroll
            for (int r = 0; r < RPT; r++) {
                float dot = xv[r][0] * c0;
                dot = fmaf(xv[r][1], c1, dot);
                dot = fmaf(xv[r][2], c2, dot);
                dot = fmaf(xv[r][3], c3, dot);
                dot = fmaf(xv[r][4], c4, dot);
                dot = fmaf(xv[r][5], c5, dot);
                // strict '>' keeps the FIRST max -> matches jnp.argmax ties
                if (dot > best[r]) { best[r] = dot; idx[r] = k; }
            }
        }

        // Emit winning codebook rows (conflict-free: bank = m % 32).
        #pragma unroll
        for (int r = 0; r < RPT; r++) {
            const int kb = idx[r] * D_SUB;
            const float o0 = cbs[(kb + 0) * M_SUB + m];
            const float o1 = cbs[(kb + 1) * M_SUB + m];
            const float o2 = cbs[(kb + 2) * M_SUB + m];
            const float o3 = cbs[(kb + 3) * M_SUB + m];
            const float o4 = cbs[(kb + 4) * M_SUB + m];
            const float o5 = cbs[(kb + 5) * M_SUB + m];
            float2* po = reinterpret_cast<float2*>(
                out + (size_t)(b0 + r) * DIM + m * D_SUB);
            po[0] = make_float2(o0, o1);
            po[1] = make_float2(o2, o3);
            po[2] = make_float2(o4, o5);
        }
    }
}

extern "C" void kernel_launch(void* const* d_in, const int* in_sizes, int n_in,
                              void* d_out, int out_size)
{
    const float* x  = (const float*)d_in[0];
    const float* cb = (const float*)d_in[1];
    float* out      = (float*)d_out;

    const int smem = CB_ELEMS * sizeof(float);   // 98304 B
    cudaFuncSetAttribute(pq_head_kernel,
                         cudaFuncAttributeMaxDynamicSharedMemorySize, smem);

    pq_head_kernel<<<NBLOCKS, TPB, smem>>>(x, cb, out);
}